// round 2
// baseline (speedup 1.0000x reference)
#include <cuda_runtime.h>

// 3x3 conv, stride 1, pad 1, single channel, X: (32, 1024, 1024) fp32.
// Register-blocked: each thread computes a 4x8 output tile (two float4 loads
// per input row -> per-thread MLP >= 2). Block = 256 threads = 128 wide x
// 2 row-subgroups, covering 8 rows x 1024 cols. Grid = 32 * 128 = 4096.

#define IMG_W 1024
#define IMG_H 1024

__global__ __launch_bounds__(256, 4) void conv3x3_kernel(
    const float* __restrict__ X,
    const float* __restrict__ Wt,
    float* __restrict__ Y)
{
    const int tid   = threadIdx.x;
    const int bx    = blockIdx.x;
    const int batch = bx >> 7;                 // / 128 row-bands
    const int band  = bx & 127;                // 8-row band index
    const int r0    = (band << 3) + ((tid >> 7) << 2);  // first output row (4-row tile)
    const int c0    = (tid & 127) << 3;        // first output col (8 cols, float4-aligned)

    const size_t plane = (size_t)IMG_W * IMG_H;
    const float* Xb = X + (size_t)batch * plane;
    float*       Yb = Y + (size_t)batch * plane;

    float w[9];
#pragma unroll
    for (int i = 0; i < 9; i++) w[i] = __ldg(Wt + i);

    float acc[4][8];
#pragma unroll
    for (int i = 0; i < 4; i++)
#pragma unroll
        for (int j = 0; j < 8; j++) acc[i][j] = 0.0f;

    // Stream 6 input rows (r0-1 .. r0+4).
#pragma unroll
    for (int rr = -1; rr <= 4; rr++) {
        const int r = r0 + rr;
        float row[10];                          // cols c0-1 .. c0+8
        if (r >= 0 && r < IMG_H) {
            const float* p = Xb + (size_t)r * IMG_W + c0;
            const float4 v0 = *reinterpret_cast<const float4*>(p);
            const float4 v1 = *reinterpret_cast<const float4*>(p + 4);
            row[1] = v0.x; row[2] = v0.y; row[3] = v0.z; row[4] = v0.w;
            row[5] = v1.x; row[6] = v1.y; row[7] = v1.z; row[8] = v1.w;
            row[0] = (c0 > 0)          ? __ldg(p - 1) : 0.0f;
            row[9] = (c0 + 8 < IMG_W)  ? __ldg(p + 8) : 0.0f;
        } else {
#pragma unroll
            for (int j = 0; j < 10; j++) row[j] = 0.0f;
        }

        // Output row i uses input rows r0+i-1 .. r0+i+1 -> ky = rr - i + 1.
#pragma unroll
        for (int i = 0; i < 4; i++) {
            const int ky = rr - i + 1;
            if (ky >= 0 && ky <= 2) {           // compile-time after unroll
#pragma unroll
                for (int j = 0; j < 8; j++) {
                    acc[i][j] = fmaf(w[ky * 3 + 0], row[j],
                                fmaf(w[ky * 3 + 1], row[j + 1],
                                fmaf(w[ky * 3 + 2], row[j + 2], acc[i][j])));
                }
            }
        }
    }

#pragma unroll
    for (int i = 0; i < 4; i++) {
        float* q = Yb + (size_t)(r0 + i) * IMG_W + c0;
        float4 o0, o1;
        o0.x = acc[i][0]; o0.y = acc[i][1]; o0.z = acc[i][2]; o0.w = acc[i][3];
        o1.x = acc[i][4]; o1.y = acc[i][5]; o1.z = acc[i][6]; o1.w = acc[i][7];
        *reinterpret_cast<float4*>(q)     = o0;
        *reinterpret_cast<float4*>(q + 4) = o1;
    }
}

extern "C" void kernel_launch(void* const* d_in, const int* in_sizes, int n_in,
                              void* d_out, int out_size)
{
    const float* X  = (const float*)d_in[0];   // (32, 1024, 1024) fp32
    const float* Wt = (const float*)d_in[1];   // (3, 3) fp32
    float* Y        = (float*)d_out;           // (32, 1024, 1024) fp32

    const int grid = 32 * 128;                 // batches * 8-row bands
    conv3x3_kernel<<<grid, 256>>>(X, Wt, Y);
}

// round 3
// speedup vs baseline: 1.1171x; 1.1171x over previous
#include <cuda_runtime.h>

// 3x3 conv, stride 1, pad 1, single channel, X: (32, 1024, 1024) fp32.
// 4x4 register tile per thread (R1 structure) + explicit double-buffered row
// prefetch so each warp keeps ~2 independent LDG.128 in flight.
// Block = 256 threads covers 4 rows x 1024 cols. Grid = 32 * 256 = 8192.

#define IMG_W 1024
#define IMG_H 1024

__global__ __launch_bounds__(256, 6) void conv3x3_kernel(
    const float* __restrict__ X,
    const float* __restrict__ Wt,
    float* __restrict__ Y)
{
    const int tid   = threadIdx.x;
    const int bx    = blockIdx.x;
    const int batch = bx >> 8;        // / 256 row-groups
    const int rg    = bx & 255;
    const int r0    = rg << 2;        // first output row of this thread's tile
    const int c0    = tid << 2;       // first output col (float4 aligned)

    const size_t plane = (size_t)IMG_W * IMG_H;
    const float* Xb = X + (size_t)batch * plane;
    float*       Yb = Y + (size_t)batch * plane;

    float w[9];
#pragma unroll
    for (int i = 0; i < 9; i++) w[i] = __ldg(Wt + i);

    float acc[4][4];
#pragma unroll
    for (int i = 0; i < 4; i++)
#pragma unroll
        for (int j = 0; j < 4; j++) acc[i][j] = 0.0f;

    // Double-buffered row registers: rows c0-1 .. c0+4 (6 floats each).
    float rowbuf[2][6];

    // Helper lambda-free load of input row r into buffer slot s.
#define LOAD_ROW(s, r)                                                        \
    do {                                                                      \
        if ((r) >= 0 && (r) < IMG_H) {                                        \
            const float* p = Xb + (size_t)(r) * IMG_W + c0;                   \
            const float4 v = *reinterpret_cast<const float4*>(p);             \
            rowbuf[s][1] = v.x; rowbuf[s][2] = v.y;                           \
            rowbuf[s][3] = v.z; rowbuf[s][4] = v.w;                           \
            rowbuf[s][0] = (c0 > 0)         ? __ldg(p - 1) : 0.0f;            \
            rowbuf[s][5] = (c0 + 4 < IMG_W) ? __ldg(p + 4) : 0.0f;            \
        } else {                                                              \
            rowbuf[s][0] = 0.0f; rowbuf[s][1] = 0.0f; rowbuf[s][2] = 0.0f;    \
            rowbuf[s][3] = 0.0f; rowbuf[s][4] = 0.0f; rowbuf[s][5] = 0.0f;    \
        }                                                                     \
    } while (0)

    // Prime the pipeline with the first row (rr = -1).
    LOAD_ROW(0, r0 - 1);

    // Stream rows rr = -1 .. 4; prefetch rr+1 before computing rr.
#pragma unroll
    for (int rr = -1; rr <= 4; rr++) {
        const int cur = (rr + 1) & 1;   // buffer holding row rr
        const int nxt = (rr + 2) & 1;   // buffer for row rr+1
        if (rr < 4) {
            LOAD_ROW(nxt, r0 + rr + 1);
        }

        // Output row i (0..3) uses input rows r0+i-1..r0+i+1 -> ky = rr-i+1.
#pragma unroll
        for (int i = 0; i < 4; i++) {
            const int ky = rr - i + 1;
            if (ky >= 0 && ky <= 2) {   // compile-time after unroll
#pragma unroll
                for (int j = 0; j < 4; j++) {
                    acc[i][j] = fmaf(w[ky * 3 + 0], rowbuf[cur][j],
                                fmaf(w[ky * 3 + 1], rowbuf[cur][j + 1],
                                fmaf(w[ky * 3 + 2], rowbuf[cur][j + 2],
                                     acc[i][j])));
                }
            }
        }
    }
#undef LOAD_ROW

#pragma unroll
    for (int i = 0; i < 4; i++) {
        float4 o;
        o.x = acc[i][0]; o.y = acc[i][1]; o.z = acc[i][2]; o.w = acc[i][3];
        *reinterpret_cast<float4*>(Yb + (size_t)(r0 + i) * IMG_W + c0) = o;
    }
}

extern "C" void kernel_launch(void* const* d_in, const int* in_sizes, int n_in,
                              void* d_out, int out_size)
{
    const float* X  = (const float*)d_in[0];   // (32, 1024, 1024) fp32
    const float* Wt = (const float*)d_in[1];   // (3, 3) fp32
    float* Y        = (float*)d_out;           // (32, 1024, 1024) fp32

    const int grid = 32 * 256;                 // batches * 4-row groups
    conv3x3_kernel<<<grid, 256>>>(X, Wt, Y);
}